// round 2
// baseline (speedup 1.0000x reference)
#include <cuda_runtime.h>
#include <cuda_bf16.h>

#define PADDING_IDX 0
#define SMOOTHING   0.1f

// Scratch for per-row partial contributions (N = 4096; padded for safety).
// __device__ global: allocation-free per harness rules.
#define MAX_ROWS 8192
__device__ float g_row_partial[MAX_ROWS];

// One block per row. Computes:
//   partial[r] = mask_r * ( -(SMOOTHING/V) * sum_v x[r,v]  -  (1-SMOOTHING) * x[r, target_r] )
// NOTE: target is int32 on device (JAX default x64-disabled downcasts int64 -> int32).
__global__ void __launch_bounds__(256)
ls_row_kernel(const float* __restrict__ x,
              const int* __restrict__ target,
              int V)
{
    const int r = blockIdx.x;
    const int t = target[r];

    // Padding row, or (defensively) any out-of-range index: contributes 0,
    // and we skip streaming the row entirely.
    if (t == PADDING_IDX || t < 0 || t >= V) {
        if (threadIdx.x == 0) g_row_partial[r] = 0.0f;
        return;
    }

    const size_t row_off = (size_t)r * (size_t)V;
    const float4* __restrict__ row4 = reinterpret_cast<const float4*>(x + row_off);
    const int nv4 = V >> 2;  // V = 32000 -> 8000 float4 (16B-aligned: V*4B row stride)

    float s = 0.0f;
    // Consecutive threads hit consecutive 16B chunks -> fully coalesced
    // 128B wavefronts; 8000/256 ~ 31 iterations -> MLP >> 4, DRAM latency hidden.
    for (int i = threadIdx.x; i < nv4; i += blockDim.x) {
        float4 v = row4[i];
        s += (v.x + v.y) + (v.z + v.w);
    }
    // Tail for V not divisible by 4 (not hit for V=32000, kept for safety)
    for (int i = (nv4 << 2) + threadIdx.x; i < V; i += blockDim.x) {
        s += x[row_off + i];
    }

    // Warp reduce
    #pragma unroll
    for (int o = 16; o > 0; o >>= 1)
        s += __shfl_down_sync(0xffffffffu, s, o);

    __shared__ float sh[8];  // 256 threads -> 8 warps
    if ((threadIdx.x & 31) == 0) sh[threadIdx.x >> 5] = s;
    __syncthreads();

    if (threadIdx.x < 32) {
        float v = (threadIdx.x < 8) ? sh[threadIdx.x] : 0.0f;
        #pragma unroll
        for (int o = 4; o > 0; o >>= 1)
            v += __shfl_down_sync(0xffffffffu, v, o);
        if (threadIdx.x == 0) {
            const float g = x[row_off + (size_t)t];  // gather (L2-hot: row just streamed)
            g_row_partial[r] = -(SMOOTHING / (float)V) * v - (1.0f - SMOOTHING) * g;
        }
    }
}

// Deterministic single-block reduction of the N row partials -> scalar.
__global__ void __launch_bounds__(1024)
ls_final_kernel(float* __restrict__ out, int n)
{
    __shared__ float sh[1024];
    float s = 0.0f;
    for (int i = threadIdx.x; i < n; i += 1024)
        s += g_row_partial[i];
    sh[threadIdx.x] = s;
    __syncthreads();
    #pragma unroll
    for (int o = 512; o > 0; o >>= 1) {
        if (threadIdx.x < o) sh[threadIdx.x] += sh[threadIdx.x + o];
        __syncthreads();
    }
    if (threadIdx.x == 0) out[0] = sh[0];
}

extern "C" void kernel_launch(void* const* d_in, const int* in_sizes, int n_in,
                              void* d_out, int out_size)
{
    const float* x      = (const float*)d_in[0];
    const int*   target = (const int*)d_in[1];
    float*       out    = (float*)d_out;

    const int N = in_sizes[1];                 // 4096 rows
    const int V = in_sizes[0] / N;             // 32000 vocab

    ls_row_kernel<<<N, 256>>>(x, target, V);
    ls_final_kernel<<<1, 1024>>>(out, N);
}